// round 11
// baseline (speedup 1.0000x reference)
#include <cuda_runtime.h>
#include <cuda_bf16.h>
#include <cstdint>

#define DI __device__ __forceinline__

// ---------------------------------------------------------------------------
// Problem:
//   x   : (N=32, C=128, T=512, F=32) fp32
//   out : (N, C, C, F) fp32
//   out[n,i,j,f] = exp(-||x[n,i,:,f]-x[n,j,:,f]||^2 / (2 sigma^2))
//
// R11: R10 structure; gram mainloop 1-sync/chunk (wait_group 1 ordering) and
//      STG.64 f-pair gather epilogue.
// ---------------------------------------------------------------------------
#define NB 32
#define CC 128
#define TT 512
#define FF 32

__device__ __align__(256) unsigned char g_x8[(size_t)NB * FF * CC * TT]; // 64 MiB

DI uint16_t fp8x2(float hi, float lo) {
    uint16_t r;
    asm("cvt.rn.satfinite.e4m3x2.f32 %0, %1, %2;" : "=h"(r) : "f"(hi), "f"(lo));
    return r;
}

// ---------------------------------------------------------------------------
// Kernel 1: (N,C,T,F) fp32 -> (N,F,C,T) e4m3.  Tile 64t x 32f.  (at BW floor)
// ---------------------------------------------------------------------------
__global__ void __launch_bounds__(256) k_transpose(const float* __restrict__ x) {
    __shared__ float tile[64][33];
    const int t0 = blockIdx.x * 64;
    const int c  = blockIdx.y;
    const int n  = blockIdx.z;
    const int lane = threadIdx.x;

    const float* src = x + (((size_t)(n * CC + c)) * TT + t0) * FF;
#pragma unroll
    for (int it = 0; it < 8; it++) {
        int t = threadIdx.y + it * 8;
        tile[t][lane] = src[(size_t)t * FF + lane];
    }
    __syncthreads();

#pragma unroll
    for (int it = 0; it < 4; it++) {
        int fi = threadIdx.y + it * 8;
        uint16_t p = fp8x2(tile[2 * lane + 1][fi], tile[2 * lane][fi]);
        *reinterpret_cast<uint16_t*>(
            g_x8 + (((size_t)(n * FF + fi)) * CC + c) * TT + t0 + 2 * lane) = p;
    }
}

// ---------------------------------------------------------------------------
// Kernel 2: fp8 gram + cluster(8) DSMEM epilogue -> direct out stores
// grid = 1024 (cluster 8 = the 8 f of one (n, fb)), block = 256
// ---------------------------------------------------------------------------
#define CHUNK      128
#define NCHUNK     4
#define ROW_BYTES  144
#define STAGE_B    (128 * ROW_BYTES)        // 18432
#define SDIAG_OFF  (3 * STAGE_B)            // 55296
#define SMEM_SZ    (SDIAG_OFF + 128 * 4)    // 55808
#define KSTRIDE    272                      // bf16 kern tile row stride
// kern tile (128*272 = 34816 B) reuses stage area post-mainloop

DI uint32_t smem_u32(const void* p) {
    uint32_t a;
    asm("{ .reg .u64 t; cvta.to.shared.u64 t, %1; cvt.u32.u64 %0, t; }"
        : "=r"(a) : "l"(p));
    return a;
}
DI void cp16(void* saddr, const void* g) {
    uint32_t a = smem_u32(saddr);
    asm volatile("cp.async.cg.shared.global [%0], [%1], 16;"
                 :: "r"(a), "l"(g) : "memory");
}
DI void cp_commit() { asm volatile("cp.async.commit_group;" ::: "memory"); }
DI void cp_wait_1() { asm volatile("cp.async.wait_group 1;" ::: "memory"); }

DI void mma_fp8(float& c0, float& c1, float& c2, float& c3,
                uint32_t a0, uint32_t a1, uint32_t a2, uint32_t a3,
                uint32_t b0, uint32_t b1) {
    asm volatile(
        "mma.sync.aligned.m16n8k32.row.col.f32.e4m3.e4m3.f32 "
        "{%0,%1,%2,%3}, {%4,%5,%6,%7}, {%8,%9}, {%0,%1,%2,%3};"
        : "+f"(c0), "+f"(c1), "+f"(c2), "+f"(c3)
        : "r"(a0), "r"(a1), "r"(a2), "r"(a3), "r"(b0), "r"(b1));
}

DI void cluster_sync() {
    asm volatile("barrier.cluster.arrive.aligned;" ::: "memory");
    asm volatile("barrier.cluster.wait.aligned;" ::: "memory");
}
DI uint32_t cluster_rank() {
    uint32_t r;
    asm("mov.u32 %0, %%cluster_ctarank;" : "=r"(r));
    return r;
}
DI uint32_t mapa_sh(uint32_t laddr, uint32_t rank) {
    uint32_t r;
    asm("mapa.shared::cluster.u32 %0, %1, %2;" : "=r"(r) : "r"(laddr), "r"(rank));
    return r;
}
DI void ld_dsmem_v2(uint32_t& a, uint32_t& b, uint32_t addr) {
    asm volatile("ld.shared::cluster.v2.b32 {%0, %1}, [%2];"
                 : "=r"(a), "=r"(b) : "r"(addr));
}

DI void load_chunk(const unsigned char* A, char* buf, int tid, int k0) {
    const int row  = tid >> 1;
    const int half = tid & 1;
    const unsigned char* g = A + (size_t)row * TT + k0 + half * 64;
    char* s = buf + row * ROW_BYTES + half * 64;
#pragma unroll
    for (int v = 0; v < 4; v++)
        cp16(s + v * 16, g + v * 16);
}

extern "C" __global__ void __launch_bounds__(256, 2) __cluster_dims__(8, 1, 1)
k_gram(const float* __restrict__ sigma, float* __restrict__ out) {
    extern __shared__ char smem[];
    const uint32_t sb = smem_u32(smem);
    const int tid  = threadIdx.x;
    const int wid  = tid >> 5;
    const int lane = tid & 31;
    const int g    = lane >> 2;
    const int c4   = lane & 3;
    const int bid  = blockIdx.x;
    const int n    = bid >> 5;
    const int fb   = (bid >> 3) & 3;

    const int RM = (wid >> 2) * 64;
    const int CN = (wid & 3) * 32;

    const unsigned char* A = g_x8 + (size_t)bid * CC * TT;

    float acc[4][4][4];
#pragma unroll
    for (int mt = 0; mt < 4; mt++)
#pragma unroll
        for (int nt = 0; nt < 4; nt++)
#pragma unroll
            for (int r = 0; r < 4; r++) acc[mt][nt][r] = 0.f;

    // ---- mainloop: 1 sync per chunk ----
    load_chunk(A, smem + 0 * STAGE_B, tid, 0 * CHUNK);
    cp_commit();
    load_chunk(A, smem + 1 * STAGE_B, tid, 1 * CHUNK);
    cp_commit();

#pragma unroll 1
    for (int k = 0; k < NCHUNK; k++) {
        cp_wait_1();              // chunk k landed (chunk k+1 may pend)
        __syncthreads();          // everyone done with chunk k-1's stage
        if (k + 2 < NCHUNK)       // overwrites stage (k-1)%3 -- safe post-sync
            load_chunk(A, smem + ((k + 2) % 3) * STAGE_B, tid, (k + 2) * CHUNK);
        cp_commit();              // empty group fine; keeps wait count exact

        const char* buf = smem + (k % 3) * STAGE_B;
#pragma unroll
        for (int ks = 0; ks < 4; ks++) {
            const int kb = ks * 32 + c4 * 4;
            uint32_t af[4][4];
#pragma unroll
            for (int mt = 0; mt < 4; mt++) {
                const char* r0 = buf + (RM + mt * 16 + g) * ROW_BYTES;
                af[mt][0] = *(const uint32_t*)(r0 + kb);
                af[mt][1] = *(const uint32_t*)(r0 + 8 * ROW_BYTES + kb);
                af[mt][2] = *(const uint32_t*)(r0 + kb + 16);
                af[mt][3] = *(const uint32_t*)(r0 + 8 * ROW_BYTES + kb + 16);
            }
            uint32_t bf[4][2];
#pragma unroll
            for (int nt = 0; nt < 4; nt++) {
                const char* r0 = buf + (CN + nt * 8 + g) * ROW_BYTES;
                bf[nt][0] = *(const uint32_t*)(r0 + kb);
                bf[nt][1] = *(const uint32_t*)(r0 + kb + 16);
            }
#pragma unroll
            for (int mt = 0; mt < 4; mt++)
#pragma unroll
                for (int nt = 0; nt < 4; nt++)
                    mma_fp8(acc[mt][nt][0], acc[mt][nt][1],
                            acc[mt][nt][2], acc[mt][nt][3],
                            af[mt][0], af[mt][1], af[mt][2], af[mt][3],
                            bf[nt][0], bf[nt][1]);
        }
    }

    // ---- epilogue: exp -> bf16 kern tile in OWN smem ----
    float* sdiag = reinterpret_cast<float*>(smem + SDIAG_OFF);

#pragma unroll
    for (int mt = 0; mt < 4; mt++)
#pragma unroll
        for (int nt = 0; nt < 4; nt++)
#pragma unroll
            for (int r = 0; r < 4; r++) {
                const int i = RM + mt * 16 + g + ((r >> 1) << 3);
                const int j = CN + nt * 8 + c4 * 2 + (r & 1);
                if (i == j) sdiag[i] = acc[mt][nt][r];
            }
    __syncthreads();              // also: all warps done with last chunk stage

    const float sg   = sigma[0];
    const float ninv = -0.5f / (sg * sg);

    float dj[4][2];
#pragma unroll
    for (int nt = 0; nt < 4; nt++) {
        dj[nt][0] = sdiag[CN + nt * 8 + c4 * 2];
        dj[nt][1] = sdiag[CN + nt * 8 + c4 * 2 + 1];
    }

#pragma unroll
    for (int mt = 0; mt < 4; mt++) {
#pragma unroll
        for (int rh = 0; rh < 2; rh++) {
            const int i  = RM + mt * 16 + g + rh * 8;
            const float di = sdiag[i];
            char* row = smem + i * KSTRIDE;
#pragma unroll
            for (int nt = 0; nt < 4; nt++) {
                const int j0 = CN + nt * 8 + c4 * 2;
                const float g0 = acc[mt][nt][rh * 2 + 0];
                const float g1 = acc[mt][nt][rh * 2 + 1];
                const float a0 = fmaxf(di + dj[nt][0] - 2.0f * g0, 0.0f) * ninv;
                const float a1 = fmaxf(di + dj[nt][1] - 2.0f * g1, 0.0f) * ninv;
                float v0 = 0.0f, v1 = 0.0f;
                if (a0 > -105.0f) v0 = __expf(a0);   // underflow -> exact 0
                if (a1 > -105.0f) v1 = __expf(a1);
                __nv_bfloat162 p = __floats2bfloat162_rn(v0, v1);
                *reinterpret_cast<uint32_t*>(row + j0 * 2) =
                    *reinterpret_cast<uint32_t*>(&p);
            }
        }
    }
    __syncthreads();
    cluster_sync();        // all 8 kern tiles visible cluster-wide

    // ---- DSMEM gather, f-pair STG.64 ----
    // rank owns rows [16r, 16r+16).  lane: fp = lane&3 -> peers 2fp, 2fp+1;
    // jq = lane>>2 -> j quad.  Warp store: 8 j x (4 f-pair lanes) = 8 dense
    // 32B sectors, 256B payload per instruction.
    const uint32_t rank = cluster_rank();
    const int      fp   = lane & 3;
    const int      jq   = lane >> 2;
    const uint32_t peerA = mapa_sh(sb, (uint32_t)(2 * fp));
    const uint32_t peerB = mapa_sh(sb, (uint32_t)(2 * fp + 1));

    float* ob = out + ((size_t)n * CC * CC) * FF + fb * 8 + 2 * fp;

#pragma unroll
    for (int ih = 0; ih < 2; ih++) {
        const int i = (int)rank * 16 + wid * 2 + ih;
        const uint32_t rowoff = (uint32_t)i * KSTRIDE;
        float* orow = ob + (size_t)i * CC * FF;
#pragma unroll
        for (int jb = 0; jb < 4; jb++) {
            const int j = jb * 32 + jq * 4;
            uint32_t a0, a1, b0, b1;
            ld_dsmem_v2(a0, a1, peerA + rowoff + (uint32_t)j * 2); // fA: j..j+3
            ld_dsmem_v2(b0, b1, peerB + rowoff + (uint32_t)j * 2); // fB: j..j+3
            // bf16 -> f32 exact via <<16 ; store (fA,fB) pairs
            float2 s0 = make_float2(__uint_as_float(a0 << 16),
                                    __uint_as_float(b0 << 16));
            float2 s1 = make_float2(__uint_as_float(a0 & 0xFFFF0000u),
                                    __uint_as_float(b0 & 0xFFFF0000u));
            float2 s2 = make_float2(__uint_as_float(a1 << 16),
                                    __uint_as_float(b1 << 16));
            float2 s3 = make_float2(__uint_as_float(a1 & 0xFFFF0000u),
                                    __uint_as_float(b1 & 0xFFFF0000u));
            *reinterpret_cast<float2*>(orow + (size_t)(j + 0) * FF) = s0;
            *reinterpret_cast<float2*>(orow + (size_t)(j + 1) * FF) = s1;
            *reinterpret_cast<float2*>(orow + (size_t)(j + 2) * FF) = s2;
            *reinterpret_cast<float2*>(orow + (size_t)(j + 3) * FF) = s3;
        }
    }

    cluster_sync();        // nobody exits while peers read our smem
}

// ---------------------------------------------------------------------------
// launch
// ---------------------------------------------------------------------------
extern "C" void kernel_launch(void* const* d_in, const int* in_sizes, int n_in,
                              void* d_out, int out_size) {
    const float* x     = (const float*)d_in[0];
    const float* sigma = (const float*)d_in[1];
    float* out         = (float*)d_out;
    (void)in_sizes; (void)n_in; (void)out_size;

    dim3 g1(TT / 64, CC, NB), b1(32, 8);
    k_transpose<<<g1, b1>>>(x);

    cudaFuncSetAttribute(k_gram, cudaFuncAttributeMaxDynamicSharedMemorySize, SMEM_SZ);
    k_gram<<<NB * FF, 256, SMEM_SZ>>>(sigma, out);
}